// round 11
// baseline (speedup 1.0000x reference)
#include <cuda_runtime.h>

#define Bn  32
#define Hn  1024
#define Vn  32000
#define Tn  128
#define K2n 2048
#define H3n 3072

typedef unsigned long long ull;

// ---------------- scratch (device globals; no allocations allowed) ----------
__device__ float g_h[2 * Bn * Hn];      // [gru][b][H] current hidden
__device__ float g_hcat[Bn * K2n];      // [b][2H] concat(h_f, h_b)
__device__ float g_gi[2 * Bn * H3n];    // [gru][b][3H]
__device__ float g_gh[2 * Bn * H3n];    // [gru][b][3H]
__device__ int   g_dec[Bn];             // current decoder input tokens
__device__ float g_lse[Bn];             // per-row logsumexp

__device__ __forceinline__ ull fma2(ull a, ull b, ull c) {
    ull d;
    asm("fma.rn.f32x2 %0, %1, %2, %3;" : "=l"(d) : "l"(a), "l"(b), "l"(c));
    return d;
}

// ---------------- init: h <- hidden, dec <- inputs[:,0] ---------------------
__global__ void init_kernel(const int* __restrict__ inputs,
                            const float* __restrict__ hidden) {
    int idx = blockIdx.x * blockDim.x + threadIdx.x;
    if (idx < 2 * Bn * Hn) g_h[idx] = hidden[idx];
    if (idx < Bn) g_dec[idx] = inputs[idx];
}

// ---------------- gates: gi/gh = {x,h} @ W^T + b for both GRUs --------------
// 4 matrices (w_ih_f, w_hh_f, w_ih_b, w_hh_b), each 3072 rows, K=1024.
// grid = 4 * 24 blocks, 128 threads. Block tile: 128 rows x 32 batches.
// Micro-tile per thread: 8 rows x 4 batches, accumulators packed f32x2.
__global__ __launch_bounds__(128) void gates_kernel(
    const float* __restrict__ emb,
    const float* __restrict__ wihf, const float* __restrict__ whhf,
    const float* __restrict__ bihf, const float* __restrict__ bhhf,
    const float* __restrict__ wihb, const float* __restrict__ whhb,
    const float* __restrict__ bihb, const float* __restrict__ bhhb) {
    constexpr int RT = 128, KC = 16, K = Hn, NK = K / KC;
    const int m = blockIdx.x / 24;
    const int rbase = (blockIdx.x % 24) * RT;

    const float* W; const float* bias; float* C; int useX = 0; int hoff = 0;
    if (m == 0)      { W = wihf; bias = bihf; C = g_gi;             useX = 1; }
    else if (m == 1) { W = whhf; bias = bhhf; C = g_gh;             hoff = 0; }
    else if (m == 2) { W = wihb; bias = bihb; C = g_gi + Bn * H3n;  useX = 1; }
    else             { W = whhb; bias = bhhb; C = g_gh + Bn * H3n;  hoff = Bn * Hn; }

    __shared__ __align__(16) float Ws[2][KC][RT + 4];   // [k][row]
    __shared__ __align__(16) float Asd[2][KC][68];      // [k][2b] duplicated

    const int tid = threadIdx.x;
    const int bg = tid & 7, rg = tid >> 3;     // rg 0..15, bg 0..7
    const int lb = tid >> 2, kq = tid & 3;     // A loader: b 0..31, kq 0..3
    const float* arow = useX ? (emb + (size_t)g_dec[lb] * Hn)
                             : (g_h + hoff + lb * Hn);
    const float* wbase = W + (size_t)(rbase + (tid >> 2)) * K + kq * 4;

    ull acc[4][4];
#pragma unroll
    for (int rp = 0; rp < 4; ++rp) {
        ull bv = *(const ull*)(bias + rbase + rg * 8 + 2 * rp);
#pragma unroll
        for (int b = 0; b < 4; ++b) acc[rp][b] = bv;
    }

    float4 wst[4]; float4 ast;
#pragma unroll
    for (int it = 0; it < 4; ++it)
        wst[it] = *(const float4*)(wbase + (size_t)it * 32 * K);
    ast = *(const float4*)(arow + kq * 4);

    int buf = 0;
    for (int c = 0; c < NK; ++c) {
        // stage -> smem (transposed)
#pragma unroll
        for (int it = 0; it < 4; ++it) {
            int r = (tid >> 2) + it * 32;
            Ws[buf][kq * 4 + 0][r] = wst[it].x;
            Ws[buf][kq * 4 + 1][r] = wst[it].y;
            Ws[buf][kq * 4 + 2][r] = wst[it].z;
            Ws[buf][kq * 4 + 3][r] = wst[it].w;
        }
        {
            int bb = 2 * lb;
            Asd[buf][kq * 4 + 0][bb] = ast.x; Asd[buf][kq * 4 + 0][bb + 1] = ast.x;
            Asd[buf][kq * 4 + 1][bb] = ast.y; Asd[buf][kq * 4 + 1][bb + 1] = ast.y;
            Asd[buf][kq * 4 + 2][bb] = ast.z; Asd[buf][kq * 4 + 2][bb + 1] = ast.z;
            Asd[buf][kq * 4 + 3][bb] = ast.w; Asd[buf][kq * 4 + 3][bb + 1] = ast.w;
        }
        __syncthreads();
        if (c + 1 < NK) {
            int kc = (c + 1) * KC;
#pragma unroll
            for (int it = 0; it < 4; ++it)
                wst[it] = *(const float4*)(wbase + (size_t)it * 32 * K + kc);
            ast = *(const float4*)(arow + kc + kq * 4);
        }
#pragma unroll
        for (int k = 0; k < KC; ++k) {
            ulonglong2 w01 = *(const ulonglong2*)&Ws[buf][k][rg * 8];
            ulonglong2 w23 = *(const ulonglong2*)&Ws[buf][k][rg * 8 + 4];
            ulonglong2 a01 = *(const ulonglong2*)&Asd[buf][k][bg * 8];
            ulonglong2 a23 = *(const ulonglong2*)&Asd[buf][k][bg * 8 + 4];
            ull wp[4] = {w01.x, w01.y, w23.x, w23.y};
            ull ad[4] = {a01.x, a01.y, a23.x, a23.y};
#pragma unroll
            for (int rp = 0; rp < 4; ++rp)
#pragma unroll
                for (int b = 0; b < 4; ++b)
                    acc[rp][b] = fma2(wp[rp], ad[b], acc[rp][b]);
        }
        buf ^= 1;
    }

#pragma unroll
    for (int rp = 0; rp < 4; ++rp)
#pragma unroll
        for (int b = 0; b < 4; ++b) {
            int v = rbase + rg * 8 + 2 * rp;
            int ba = bg * 4 + b;
            *(ull*)(C + (size_t)ba * H3n + v) = acc[rp][b];  // stores (v, v+1)
        }
}

// ---------------- GRU gate combine + hidden update --------------------------
__global__ __launch_bounds__(256) void hupdate_kernel() {
    int idx = blockIdx.x * blockDim.x + threadIdx.x;  // 2*B*H = 65536
    int g = idx >> 15;
    int rem = idx & 32767;
    int b = rem >> 10;
    int i = rem & 1023;
    const float* gi = g_gi + ((size_t)g * Bn + b) * H3n;
    const float* gh = g_gh + ((size_t)g * Bn + b) * H3n;
    float ir = gi[i], iz = gi[i + Hn], inn = gi[i + 2 * Hn];
    float hr = gh[i], hz = gh[i + Hn], hn = gh[i + 2 * Hn];
    float r = 1.f / (1.f + expf(-(ir + hr)));
    float z = 1.f / (1.f + expf(-(iz + hz)));
    float n = tanhf(inn + r * hn);
    int hidx = (g * Bn + b) * Hn + i;
    float h = g_h[hidx];
    h = (1.f - z) * n + z * h;
    g_h[hidx] = h;
    g_hcat[b * K2n + g * Hn + i] = h;
}

// ---------------- logits: out[b][t][v] = hcat[b] . w_out[v] + b_out[v] -----
// grid = 143 blocks (RT=224 rows), 224 threads. K = 2048.
__global__ __launch_bounds__(224) void logits_kernel(
    const float* __restrict__ wout, const float* __restrict__ bout,
    float* __restrict__ out, int t) {
    constexpr int RT = 224, KC = 16, K = K2n, NK = K / KC;
    const int rbase = blockIdx.x * RT;

    __shared__ __align__(16) float Ws[2][KC][RT + 4];
    __shared__ __align__(16) float Asd[2][KC][68];

    const int tid = threadIdx.x;
    const int bg = tid & 7, rg = tid >> 3;       // rg 0..27
    const int lb = tid >> 2, kq = tid & 3;
    const bool doA = (tid < 128);                // lb 0..31 valid
    const float* arow = g_hcat + (size_t)(doA ? lb : 0) * K2n;
    const int wr = tid >> 2;                     // 0..55, rows wr + it*56

    ull acc[4][4];
#pragma unroll
    for (int rp = 0; rp < 4; ++rp) {
        int v0 = rbase + rg * 8 + 2 * rp;
        if (v0 > Vn - 2) v0 = Vn - 2;
        ull bv = *(const ull*)(bout + v0);
#pragma unroll
        for (int b = 0; b < 4; ++b) acc[rp][b] = bv;
    }

    float4 wst[4]; float4 ast;
#pragma unroll
    for (int it = 0; it < 4; ++it) {
        int gr = rbase + wr + it * 56; if (gr > Vn - 1) gr = Vn - 1;
        wst[it] = *(const float4*)(wout + (size_t)gr * K + kq * 4);
    }
    if (doA) ast = *(const float4*)(arow + kq * 4);

    int buf = 0;
    for (int c = 0; c < NK; ++c) {
#pragma unroll
        for (int it = 0; it < 4; ++it) {
            int r = wr + it * 56;
            Ws[buf][kq * 4 + 0][r] = wst[it].x;
            Ws[buf][kq * 4 + 1][r] = wst[it].y;
            Ws[buf][kq * 4 + 2][r] = wst[it].z;
            Ws[buf][kq * 4 + 3][r] = wst[it].w;
        }
        if (doA) {
            int bb = 2 * lb;
            Asd[buf][kq * 4 + 0][bb] = ast.x; Asd[buf][kq * 4 + 0][bb + 1] = ast.x;
            Asd[buf][kq * 4 + 1][bb] = ast.y; Asd[buf][kq * 4 + 1][bb + 1] = ast.y;
            Asd[buf][kq * 4 + 2][bb] = ast.z; Asd[buf][kq * 4 + 2][bb + 1] = ast.z;
            Asd[buf][kq * 4 + 3][bb] = ast.w; Asd[buf][kq * 4 + 3][bb + 1] = ast.w;
        }
        __syncthreads();
        if (c + 1 < NK) {
            int kc = (c + 1) * KC;
#pragma unroll
            for (int it = 0; it < 4; ++it) {
                int gr = rbase + wr + it * 56; if (gr > Vn - 1) gr = Vn - 1;
                wst[it] = *(const float4*)(wout + (size_t)gr * K + kc + kq * 4);
            }
            if (doA) ast = *(const float4*)(arow + kc + kq * 4);
        }
#pragma unroll
        for (int k = 0; k < KC; ++k) {
            ulonglong2 w01 = *(const ulonglong2*)&Ws[buf][k][rg * 8];
            ulonglong2 w23 = *(const ulonglong2*)&Ws[buf][k][rg * 8 + 4];
            ulonglong2 a01 = *(const ulonglong2*)&Asd[buf][k][bg * 8];
            ulonglong2 a23 = *(const ulonglong2*)&Asd[buf][k][bg * 8 + 4];
            ull wp[4] = {w01.x, w01.y, w23.x, w23.y};
            ull ad[4] = {a01.x, a01.y, a23.x, a23.y};
#pragma unroll
            for (int rp = 0; rp < 4; ++rp)
#pragma unroll
                for (int b = 0; b < 4; ++b)
                    acc[rp][b] = fma2(wp[rp], ad[b], acc[rp][b]);
        }
        buf ^= 1;
    }

#pragma unroll
    for (int rp = 0; rp < 4; ++rp) {
        int v = rbase + rg * 8 + 2 * rp;
        if (v < Vn) {
#pragma unroll
            for (int b = 0; b < 4; ++b) {
                int ba = bg * 4 + b;
                *(ull*)(out + (size_t)ba * Tn * Vn + (size_t)t * Vn + v) = acc[rp][b];
            }
        }
    }
}

// ---------------- per-row max/argmax + logsumexp ----------------------------
__global__ __launch_bounds__(512) void reduce_kernel(const float* __restrict__ out,
                                                     int t) {
    const int b = blockIdx.x;
    const float* row = out + (size_t)b * Tn * Vn + (size_t)t * Vn;
    const float4* row4 = (const float4*)row;
    __shared__ float sm[512];
    __shared__ int si[512];
    const int tid = threadIdx.x;

    float m = -3.4e38f; int mi = 0;
    for (int i = tid; i < Vn / 4; i += 512) {
        float4 v = row4[i];
        if (v.x > m) { m = v.x; mi = 4 * i; }
        if (v.y > m) { m = v.y; mi = 4 * i + 1; }
        if (v.z > m) { m = v.z; mi = 4 * i + 2; }
        if (v.w > m) { m = v.w; mi = 4 * i + 3; }
    }
    sm[tid] = m; si[tid] = mi;
    __syncthreads();
    for (int s = 256; s > 0; s >>= 1) {
        if (tid < s) {
            float vo = sm[tid + s]; int io = si[tid + s];
            if (vo > sm[tid] || (vo == sm[tid] && io < si[tid])) {
                sm[tid] = vo; si[tid] = io;
            }
        }
        __syncthreads();
    }
    float mx = sm[0]; int am = si[0];
    __syncthreads();

    float s = 0.f;
    for (int i = tid; i < Vn / 4; i += 512) {
        float4 v = row4[i];
        s += expf(v.x - mx) + expf(v.y - mx) + expf(v.z - mx) + expf(v.w - mx);
    }
    sm[tid] = s;
    __syncthreads();
    for (int st = 256; st > 0; st >>= 1) {
        if (tid < st) sm[tid] += sm[tid + st];
        __syncthreads();
    }
    if (tid == 0) {
        g_dec[b] = am;
        g_lse[b] = mx + logf(sm[0]);
    }
}

// ---------------- logits -> logp in place -----------------------------------
__global__ __launch_bounds__(256) void fix_kernel(float* __restrict__ out, int t) {
    int idx = blockIdx.x * blockDim.x + threadIdx.x;  // B * V/4 = 256000
    if (idx >= Bn * (Vn / 4)) return;
    int b = idx / (Vn / 4);
    int j = idx - b * (Vn / 4);
    float l = g_lse[b];
    float4* p = (float4*)(out + (size_t)b * Tn * Vn + (size_t)t * Vn + 4 * (size_t)j);
    float4 v = *p;
    v.x -= l; v.y -= l; v.z -= l; v.w -= l;
    *p = v;
}

// ---------------- host ------------------------------------------------------
extern "C" void kernel_launch(void* const* d_in, const int* in_sizes, int n_in,
                              void* d_out, int out_size) {
    const int*   inputs = (const int*)d_in[0];
    const float* hidden = (const float*)d_in[1];
    const float* emb    = (const float*)d_in[2];
    const float* wihf   = (const float*)d_in[3];
    const float* whhf   = (const float*)d_in[4];
    const float* bihf   = (const float*)d_in[5];
    const float* bhhf   = (const float*)d_in[6];
    const float* wihb   = (const float*)d_in[7];
    const float* whhb   = (const float*)d_in[8];
    const float* bihb   = (const float*)d_in[9];
    const float* bhhb   = (const float*)d_in[10];
    const float* wout   = (const float*)d_in[11];
    const float* bout   = (const float*)d_in[12];
    float* out = (float*)d_out;

    init_kernel<<<256, 256>>>(inputs, hidden);
    for (int t = 0; t < Tn; ++t) {
        gates_kernel<<<96, 128>>>(emb, wihf, whhf, bihf, bhhf,
                                  wihb, whhb, bihb, bhhb);
        hupdate_kernel<<<256, 256>>>();
        logits_kernel<<<143, 224>>>(wout, bout, out, t);
        reduce_kernel<<<32, 512>>>(out, t);
        fix_kernel<<<1000, 256>>>(out, t);
    }
}

// round 12
// speedup vs baseline: 1.5371x; 1.5371x over previous
#include <cuda_runtime.h>

#define Bn  32
#define Hn  1024
#define Vn  32000
#define Tn  128
#define K2n 2048
#define H3n 3072

typedef unsigned long long ull;

// ---------------- scratch (device globals; no allocations allowed) ----------
__device__ float g_h[2 * Bn * Hn];      // [gru][b][H] current hidden
__device__ float g_hcat[Bn * K2n];      // [b][2H] concat(h_f, h_b)
__device__ float g_gi[2 * Bn * H3n];    // [gru][b][3H] partial ks=0
__device__ float g_gh[2 * Bn * H3n];
__device__ float g_giB[2 * Bn * H3n];   // partial ks=1
__device__ float g_ghB[2 * Bn * H3n];
__device__ float g_part[Bn * Vn];       // logits K-split partial (ks=1)
__device__ int   g_dec[Bn];             // current decoder input tokens
__device__ float g_lse[Bn];             // per-row logsumexp

__device__ __forceinline__ ull fma2(ull a, ull b, ull c) {
    ull d;
    asm("fma.rn.f32x2 %0, %1, %2, %3;" : "=l"(d) : "l"(a), "l"(b), "l"(c));
    return d;
}

// ---------------- init: h <- hidden, dec <- inputs[:,0] ---------------------
__global__ void init_kernel(const int* __restrict__ inputs,
                            const float* __restrict__ hidden) {
    int idx = blockIdx.x * blockDim.x + threadIdx.x;
    if (idx < 2 * Bn * Hn) g_h[idx] = hidden[idx];
    if (idx < Bn) g_dec[idx] = inputs[idx];
}

// ---------------- gates: gi/gh = {x,h} @ W^T + b for both GRUs --------------
// 4 matrices, each 3072 rows, K=1024, K-split 2 (512 per block).
// grid = 2 * 4 * 24 = 192 blocks, 128 threads. Tile: 128 rows x 32 batches.
__global__ __launch_bounds__(128) void gates_kernel(
    const float* __restrict__ emb,
    const float* __restrict__ wihf, const float* __restrict__ whhf,
    const float* __restrict__ bihf, const float* __restrict__ bhhf,
    const float* __restrict__ wihb, const float* __restrict__ whhb,
    const float* __restrict__ bihb, const float* __restrict__ bhhb) {
    constexpr int RT = 128, KC = 16, K = Hn, KH = 512, NK = KH / KC;
    const int ks = blockIdx.x / 96;
    const int m4 = blockIdx.x % 96;
    const int m = m4 / 24;
    const int rbase = (m4 % 24) * RT;
    const int koff = ks * KH;

    const float* W; const float* bias; float* C; int useX = 0; int hoff = 0;
    if (m == 0)      { W = wihf; bias = bihf; C = (ks ? g_giB : g_gi);             useX = 1; }
    else if (m == 1) { W = whhf; bias = bhhf; C = (ks ? g_ghB : g_gh);             hoff = 0; }
    else if (m == 2) { W = wihb; bias = bihb; C = (ks ? g_giB : g_gi) + Bn * H3n;  useX = 1; }
    else             { W = whhb; bias = bhhb; C = (ks ? g_ghB : g_gh) + Bn * H3n;  hoff = Bn * Hn; }

    __shared__ __align__(16) float Ws[2][KC][RT + 4];   // [k][row]
    __shared__ __align__(16) float Asd[2][KC][68];      // [k][2b] duplicated

    const int tid = threadIdx.x;
    const int bg = tid & 7, rg = tid >> 3;     // rg 0..15, bg 0..7
    const int lb = tid >> 2, kq = tid & 3;     // A loader: b 0..31, kq 0..3
    const float* arow = (useX ? (emb + (size_t)g_dec[lb] * Hn)
                              : (g_h + hoff + lb * Hn)) + koff;
    const float* wbase = W + (size_t)(rbase + (tid >> 2)) * K + koff + kq * 4;

    ull acc[4][4];
#pragma unroll
    for (int rp = 0; rp < 4; ++rp) {
        ull bv = 0;
        if (ks == 0) bv = *(const ull*)(bias + rbase + rg * 8 + 2 * rp);
#pragma unroll
        for (int b = 0; b < 4; ++b) acc[rp][b] = bv;
    }

    float4 wst[4]; float4 ast;
#pragma unroll
    for (int it = 0; it < 4; ++it)
        wst[it] = *(const float4*)(wbase + (size_t)it * 32 * K);
    ast = *(const float4*)(arow + kq * 4);

    int buf = 0;
    for (int c = 0; c < NK; ++c) {
#pragma unroll
        for (int it = 0; it < 4; ++it) {
            int r = (tid >> 2) + it * 32;
            Ws[buf][kq * 4 + 0][r] = wst[it].x;
            Ws[buf][kq * 4 + 1][r] = wst[it].y;
            Ws[buf][kq * 4 + 2][r] = wst[it].z;
            Ws[buf][kq * 4 + 3][r] = wst[it].w;
        }
        {
            int bb = 2 * lb;
            Asd[buf][kq * 4 + 0][bb] = ast.x; Asd[buf][kq * 4 + 0][bb + 1] = ast.x;
            Asd[buf][kq * 4 + 1][bb] = ast.y; Asd[buf][kq * 4 + 1][bb + 1] = ast.y;
            Asd[buf][kq * 4 + 2][bb] = ast.z; Asd[buf][kq * 4 + 2][bb + 1] = ast.z;
            Asd[buf][kq * 4 + 3][bb] = ast.w; Asd[buf][kq * 4 + 3][bb + 1] = ast.w;
        }
        __syncthreads();
        if (c + 1 < NK) {
            int kc = (c + 1) * KC;
#pragma unroll
            for (int it = 0; it < 4; ++it)
                wst[it] = *(const float4*)(wbase + (size_t)it * 32 * K + kc);
            ast = *(const float4*)(arow + kc + kq * 4);
        }
#pragma unroll
        for (int k = 0; k < KC; ++k) {
            ulonglong2 w01 = *(const ulonglong2*)&Ws[buf][k][rg * 8];
            ulonglong2 w23 = *(const ulonglong2*)&Ws[buf][k][rg * 8 + 4];
            ulonglong2 a01 = *(const ulonglong2*)&Asd[buf][k][bg * 8];
            ulonglong2 a23 = *(const ulonglong2*)&Asd[buf][k][bg * 8 + 4];
            ull wp[4] = {w01.x, w01.y, w23.x, w23.y};
            ull ad[4] = {a01.x, a01.y, a23.x, a23.y};
#pragma unroll
            for (int rp = 0; rp < 4; ++rp)
#pragma unroll
                for (int b = 0; b < 4; ++b)
                    acc[rp][b] = fma2(wp[rp], ad[b], acc[rp][b]);
        }
        buf ^= 1;
    }

#pragma unroll
    for (int rp = 0; rp < 4; ++rp)
#pragma unroll
        for (int b = 0; b < 4; ++b) {
            int v = rbase + rg * 8 + 2 * rp;
            int ba = bg * 4 + b;
            *(ull*)(C + (size_t)ba * H3n + v) = acc[rp][b];
        }
}

// ---------------- GRU gate combine + hidden update --------------------------
__global__ __launch_bounds__(256) void hupdate_kernel() {
    int idx = blockIdx.x * blockDim.x + threadIdx.x;  // 2*B*H = 65536
    int g = idx >> 15;
    int rem = idx & 32767;
    int b = rem >> 10;
    int i = rem & 1023;
    size_t base = ((size_t)g * Bn + b) * H3n;
    const float* gi  = g_gi  + base;
    const float* gh  = g_gh  + base;
    const float* giB = g_giB + base;
    const float* ghB = g_ghB + base;
    float ir = gi[i] + giB[i];
    float iz = gi[i + Hn] + giB[i + Hn];
    float inn = gi[i + 2 * Hn] + giB[i + 2 * Hn];
    float hr = gh[i] + ghB[i];
    float hz = gh[i + Hn] + ghB[i + Hn];
    float hn = gh[i + 2 * Hn] + ghB[i + 2 * Hn];
    float r = 1.f / (1.f + expf(-(ir + hr)));
    float z = 1.f / (1.f + expf(-(iz + hz)));
    float n = tanhf(inn + r * hn);
    int hidx = (g * Bn + b) * Hn + i;
    float h = g_h[hidx];
    h = (1.f - z) * n + z * h;
    g_h[hidx] = h;
    g_hcat[b * K2n + g * Hn + i] = h;
}

// ---------------- logits: out[b][t][v] = hcat[b] . w_out[v] + b_out[v] -----
// grid = 125 row-blocks x 2 K-splits = 250 blocks, 128 threads.
// Per-thread micro-tile: 8 rows (4 f32x2 pairs) x 8 batches, K=1024 per block.
__global__ __launch_bounds__(128, 3) void logits_kernel(
    const float* __restrict__ wout, const float* __restrict__ bout,
    float* __restrict__ out, int t) {
    constexpr int RT = 256, KC = 16, KH = 1024, NK = KH / KC;  // NK=64
    const int rb = blockIdx.x % 125;
    const int ks = blockIdx.x / 125;
    const int rbase = rb * RT;
    const int koff = ks * KH;

    __shared__ __align__(16) float Ws[2][KC][RT + 4];   // 33.3 KB
    __shared__ __align__(16) float Asd[2][KC][76];      // skewed: b -> 2b+4*(b>>3)

    const int tid = threadIdx.x;
    const int bg = tid & 3;        // batch group: batches 8*bg..8*bg+7
    const int rg = tid >> 2;       // 0..31: rows rg*8..rg*8+7
    const int lb = tid >> 2;       // A loader: batch 0..31
    const int kq = tid & 3;        // k quad 0..3
    const float* arow = g_hcat + (size_t)lb * K2n + koff;
    const int wr = tid >> 2;       // 0..31, rows wr + it*32
    const float* wbase = wout + (size_t)(rbase + wr) * K2n + koff + kq * 4;

    ull acc[4][8];
#pragma unroll
    for (int rp = 0; rp < 4; ++rp) {
        ull bv = 0;
        if (ks == 0) bv = *(const ull*)(bout + rbase + rg * 8 + 2 * rp);
#pragma unroll
        for (int j = 0; j < 8; ++j) acc[rp][j] = bv;
    }

    float4 wst[8]; float4 ast;
#pragma unroll
    for (int it = 0; it < 8; ++it)
        wst[it] = *(const float4*)(wbase + (size_t)it * 32 * K2n);
    ast = *(const float4*)(arow + kq * 4);

    const int bb = 2 * lb + 4 * (lb >> 3);  // skewed pair slot for batch lb

    int buf = 0;
    for (int c = 0; c < NK; ++c) {
#pragma unroll
        for (int it = 0; it < 8; ++it) {
            int r = wr + it * 32;
            Ws[buf][kq * 4 + 0][r] = wst[it].x;
            Ws[buf][kq * 4 + 1][r] = wst[it].y;
            Ws[buf][kq * 4 + 2][r] = wst[it].z;
            Ws[buf][kq * 4 + 3][r] = wst[it].w;
        }
        {
            Asd[buf][kq * 4 + 0][bb] = ast.x; Asd[buf][kq * 4 + 0][bb + 1] = ast.x;
            Asd[buf][kq * 4 + 1][bb] = ast.y; Asd[buf][kq * 4 + 1][bb + 1] = ast.y;
            Asd[buf][kq * 4 + 2][bb] = ast.z; Asd[buf][kq * 4 + 2][bb + 1] = ast.z;
            Asd[buf][kq * 4 + 3][bb] = ast.w; Asd[buf][kq * 4 + 3][bb + 1] = ast.w;
        }
        __syncthreads();
        if (c + 1 < NK) {
            int kc = (c + 1) * KC;
#pragma unroll
            for (int it = 0; it < 8; ++it)
                wst[it] = *(const float4*)(wbase + (size_t)it * 32 * K2n + kc);
            ast = *(const float4*)(arow + kc + kq * 4);
        }
#pragma unroll
        for (int k = 0; k < KC; ++k) {
            ulonglong2 w01 = *(const ulonglong2*)&Ws[buf][k][rg * 8];
            ulonglong2 w23 = *(const ulonglong2*)&Ws[buf][k][rg * 8 + 4];
            const float* ab = &Asd[buf][k][20 * bg];
            ulonglong2 a01 = *(const ulonglong2*)(ab);
            ulonglong2 a23 = *(const ulonglong2*)(ab + 4);
            ulonglong2 a45 = *(const ulonglong2*)(ab + 8);
            ulonglong2 a67 = *(const ulonglong2*)(ab + 12);
            ull wp[4] = {w01.x, w01.y, w23.x, w23.y};
            ull ad[8] = {a01.x, a01.y, a23.x, a23.y, a45.x, a45.y, a67.x, a67.y};
#pragma unroll
            for (int rp = 0; rp < 4; ++rp)
#pragma unroll
                for (int j = 0; j < 8; ++j)
                    acc[rp][j] = fma2(wp[rp], ad[j], acc[rp][j]);
        }
        buf ^= 1;
    }

    if (ks == 0) {
#pragma unroll
        for (int rp = 0; rp < 4; ++rp) {
            int v = rbase + rg * 8 + 2 * rp;
#pragma unroll
            for (int j = 0; j < 8; ++j) {
                int ba = bg * 8 + j;
                *(ull*)(out + (size_t)ba * Tn * Vn + (size_t)t * Vn + v) = acc[rp][j];
            }
        }
    } else {
#pragma unroll
        for (int rp = 0; rp < 4; ++rp) {
            int v = rbase + rg * 8 + 2 * rp;
#pragma unroll
            for (int j = 0; j < 8; ++j) {
                int ba = bg * 8 + j;
                *(ull*)(g_part + (size_t)ba * Vn + v) = acc[rp][j];
            }
        }
    }
}

// ---------------- per-row max/argmax + logsumexp (sums the 2 partials) ------
__global__ __launch_bounds__(512) void reduce_kernel(const float* __restrict__ out,
                                                     int t) {
    const int b = blockIdx.x;
    const float4* rowA = (const float4*)(out + (size_t)b * Tn * Vn + (size_t)t * Vn);
    const float4* rowB = (const float4*)(g_part + (size_t)b * Vn);
    __shared__ float sm[512];
    __shared__ int si[512];
    const int tid = threadIdx.x;

    float m = -3.4e38f; int mi = 0;
    for (int i = tid; i < Vn / 4; i += 512) {
        float4 va = rowA[i], vb = rowB[i];
        float x0 = va.x + vb.x, x1 = va.y + vb.y, x2 = va.z + vb.z, x3 = va.w + vb.w;
        if (x0 > m) { m = x0; mi = 4 * i; }
        if (x1 > m) { m = x1; mi = 4 * i + 1; }
        if (x2 > m) { m = x2; mi = 4 * i + 2; }
        if (x3 > m) { m = x3; mi = 4 * i + 3; }
    }
    sm[tid] = m; si[tid] = mi;
    __syncthreads();
    for (int s = 256; s > 0; s >>= 1) {
        if (tid < s) {
            float vo = sm[tid + s]; int io = si[tid + s];
            if (vo > sm[tid] || (vo == sm[tid] && io < si[tid])) {
                sm[tid] = vo; si[tid] = io;
            }
        }
        __syncthreads();
    }
    float mx = sm[0]; int am = si[0];
    __syncthreads();

    float s = 0.f;
    for (int i = tid; i < Vn / 4; i += 512) {
        float4 va = rowA[i], vb = rowB[i];
        s += expf(va.x + vb.x - mx) + expf(va.y + vb.y - mx)
           + expf(va.z + vb.z - mx) + expf(va.w + vb.w - mx);
    }
    sm[tid] = s;
    __syncthreads();
    for (int st = 256; st > 0; st >>= 1) {
        if (tid < st) sm[tid] += sm[tid + st];
        __syncthreads();
    }
    if (tid == 0) {
        g_dec[b] = am;
        g_lse[b] = mx + logf(sm[0]);
    }
}

// ---------------- logits -> logp in place (adds partial, subtracts lse) -----
__global__ __launch_bounds__(256) void fix_kernel(float* __restrict__ out, int t) {
    int idx = blockIdx.x * blockDim.x + threadIdx.x;  // B * V/4 = 256000
    if (idx >= Bn * (Vn / 4)) return;
    int b = idx / (Vn / 4);
    int j = idx - b * (Vn / 4);
    float l = g_lse[b];
    float4* p = (float4*)(out + (size_t)b * Tn * Vn + (size_t)t * Vn + 4 * (size_t)j);
    const float4* q = (const float4*)(g_part + (size_t)b * Vn + 4 * (size_t)j);
    float4 v = *p; float4 w = *q;
    v.x = v.x + w.x - l; v.y = v.y + w.y - l;
    v.z = v.z + w.z - l; v.w = v.w + w.w - l;
    *p = v;
}

// ---------------- host ------------------------------------------------------
extern "C" void kernel_launch(void* const* d_in, const int* in_sizes, int n_in,
                              void* d_out, int out_size) {
    const int*   inputs = (const int*)d_in[0];
    const float* hidden = (const float*)d_in[1];
    const float* emb    = (const float*)d_in[2];
    const float* wihf   = (const float*)d_in[3];
    const float* whhf   = (const float*)d_in[4];
    const float* bihf   = (const float*)d_in[5];
    const float* bhhf   = (const float*)d_in[6];
    const float* wihb   = (const float*)d_in[7];
    const float* whhb   = (const float*)d_in[8];
    const float* bihb   = (const float*)d_in[9];
    const float* bhhb   = (const float*)d_in[10];
    const float* wout   = (const float*)d_in[11];
    const float* bout   = (const float*)d_in[12];
    float* out = (float*)d_out;

    init_kernel<<<256, 256>>>(inputs, hidden);
    for (int t = 0; t < Tn; ++t) {
        gates_kernel<<<192, 128>>>(emb, wihf, whhf, bihf, bhhf,
                                   wihb, whhb, bihb, bhhb);
        hupdate_kernel<<<256, 256>>>();
        logits_kernel<<<250, 128>>>(wout, bout, out, t);
        reduce_kernel<<<32, 512>>>(out, t);
        fix_kernel<<<1000, 256>>>(out, t);
    }
}

// round 13
// speedup vs baseline: 1.6971x; 1.1041x over previous
#include <cuda_runtime.h>

#define Bn  32
#define Hn  1024
#define Vn  32000
#define Tn  128
#define K2n 2048
#define H3n 3072

typedef unsigned long long ull;

// ---------------- scratch (device globals; no allocations allowed) ----------
__device__ float g_h[2 * Bn * Hn];      // [gru][b][H] current hidden
__device__ float g_hcat[Bn * K2n];      // [b][2H] concat(h_f, h_b)
__device__ float g_gi[2 * Bn * H3n];    // [gru][b][3H] partial ks=0 (with bias)
__device__ float g_gh[2 * Bn * H3n];
__device__ float g_giB[2 * Bn * H3n];   // partial ks=1
__device__ float g_ghB[2 * Bn * H3n];
__device__ float g_part[Bn * Vn];       // logits K-split partial (ks=1)
__device__ int   g_dec[Bn];             // current decoder input tokens
__device__ float g_lse[Bn];             // per-row logsumexp

__device__ __forceinline__ ull fma2(ull a, ull b, ull c) {
    ull d;
    asm("fma.rn.f32x2 %0, %1, %2, %3;" : "=l"(d) : "l"(a), "l"(b), "l"(c));
    return d;
}

// ---------------- init: h <- hidden, dec <- inputs[:,0] ---------------------
__global__ void init_kernel(const int* __restrict__ inputs,
                            const float* __restrict__ hidden) {
    int idx = blockIdx.x * blockDim.x + threadIdx.x;
    if (idx < 2 * Bn * Hn) g_h[idx] = hidden[idx];
    if (idx < Bn) g_dec[idx] = inputs[idx];
}

// ============================================================================
// K-vectorized GEMM pattern (f32x2 packs adjacent k):
//   block tile: RT=128 rows x 32 batches, KC=16 k-chunk, double-buffered.
//   smem natural layout, pad 20 floats/row -> conflict-free LDS.128:
//     compute rows  r = rg + 16*i  (rg = tid>>3, i<8)  banks {0,20,8,28}*4
//     compute batch b = bg + 8*j   (bg = tid&7,  j<4)  banks cover all 32
//   acc[i][j] = (sum even k, sum odd k); horizontal add in epilogue.
// ============================================================================

// ---------------- gates: gi/gh = {x,h} @ W^T (+b) for both GRUs -------------
// 4 matrices (3072 rows, K=1024), K-split 2 (KH=512). grid = 2*4*24 = 192.
__global__ __launch_bounds__(128, 3) void gates_kernel(
    const float* __restrict__ emb,
    const float* __restrict__ wihf, const float* __restrict__ whhf,
    const float* __restrict__ bihf, const float* __restrict__ bhhf,
    const float* __restrict__ wihb, const float* __restrict__ whhb,
    const float* __restrict__ bihb, const float* __restrict__ bhhb) {
    constexpr int RT = 128, KC = 16, K = Hn, KH = 512, NK = KH / KC;
    const int ks = blockIdx.x / 96;
    const int m4 = blockIdx.x % 96;
    const int m = m4 / 24;
    const int rbase = (m4 % 24) * RT;
    const int koff = ks * KH;

    const float* W; const float* bias; float* C; int useX = 0; int hoff = 0;
    if (m == 0)      { W = wihf; bias = bihf; C = (ks ? g_giB : g_gi);             useX = 1; }
    else if (m == 1) { W = whhf; bias = bhhf; C = (ks ? g_ghB : g_gh);             hoff = 0; }
    else if (m == 2) { W = wihb; bias = bihb; C = (ks ? g_giB : g_gi) + Bn * H3n;  useX = 1; }
    else             { W = whhb; bias = bhhb; C = (ks ? g_ghB : g_gh) + Bn * H3n;  hoff = Bn * Hn; }

    __shared__ __align__(16) float Ws[2][RT][20];
    __shared__ __align__(16) float As[2][Bn][20];

    const int tid = threadIdx.x;
    const int rg = tid >> 3, bg = tid & 7;   // compute map
    const int lr = tid >> 2, kq = tid & 3;   // load map

    const float* wbase = W + (size_t)(rbase + lr) * K + koff + kq * 4;
    const float* arow = (useX ? (emb + (size_t)g_dec[lr] * Hn)
                              : (g_h + hoff + lr * Hn)) + koff + kq * 4;

    ull acc[8][4];
#pragma unroll
    for (int i = 0; i < 8; ++i)
#pragma unroll
        for (int j = 0; j < 4; ++j) acc[i][j] = 0ULL;

    float4 wst[4]; float4 ast;
#pragma unroll
    for (int it = 0; it < 4; ++it)
        wst[it] = *(const float4*)(wbase + (size_t)it * 32 * K);
    ast = *(const float4*)(arow);

    int buf = 0;
    for (int c = 0; c < NK; ++c) {
#pragma unroll
        for (int it = 0; it < 4; ++it)
            *(float4*)&Ws[buf][lr + it * 32][kq * 4] = wst[it];
        *(float4*)&As[buf][lr][kq * 4] = ast;
        __syncthreads();
        if (c + 1 < NK) {
            int kc = (c + 1) * KC;
#pragma unroll
            for (int it = 0; it < 4; ++it)
                wst[it] = *(const float4*)(wbase + (size_t)it * 32 * K + kc);
            ast = *(const float4*)(arow + kc);
        }
#pragma unroll
        for (int kk = 0; kk < KC; kk += 4) {
            ulonglong2 av[4];
#pragma unroll
            for (int j = 0; j < 4; ++j)
                av[j] = *(const ulonglong2*)&As[buf][bg + 8 * j][kk];
#pragma unroll
            for (int i = 0; i < 8; ++i) {
                ulonglong2 wv = *(const ulonglong2*)&Ws[buf][rg + 16 * i][kk];
#pragma unroll
                for (int j = 0; j < 4; ++j) {
                    acc[i][j] = fma2(wv.x, av[j].x, acc[i][j]);
                    acc[i][j] = fma2(wv.y, av[j].y, acc[i][j]);
                }
            }
        }
        buf ^= 1;
    }

#pragma unroll
    for (int i = 0; i < 8; ++i) {
        int v = rbase + rg + 16 * i;
        float bb = (ks == 0) ? bias[v] : 0.f;
#pragma unroll
        for (int j = 0; j < 4; ++j) {
            int ba = bg + 8 * j;
            float2 f = *(float2*)&acc[i][j];
            C[(size_t)ba * H3n + v] = f.x + f.y + bb;
        }
    }
}

// ---------------- GRU gate combine + hidden update --------------------------
__global__ __launch_bounds__(256) void hupdate_kernel() {
    int idx = blockIdx.x * blockDim.x + threadIdx.x;  // 2*B*H = 65536
    int g = idx >> 15;
    int rem = idx & 32767;
    int b = rem >> 10;
    int i = rem & 1023;
    size_t base = ((size_t)g * Bn + b) * H3n;
    const float* gi  = g_gi  + base;
    const float* gh  = g_gh  + base;
    const float* giB = g_giB + base;
    const float* ghB = g_ghB + base;
    float ir = gi[i] + giB[i];
    float iz = gi[i + Hn] + giB[i + Hn];
    float inn = gi[i + 2 * Hn] + giB[i + 2 * Hn];
    float hr = gh[i] + ghB[i];
    float hz = gh[i + Hn] + ghB[i + Hn];
    float hn = gh[i + 2 * Hn] + ghB[i + 2 * Hn];
    float r = 1.f / (1.f + expf(-(ir + hr)));
    float z = 1.f / (1.f + expf(-(iz + hz)));
    float n = tanhf(inn + r * hn);
    int hidx = (g * Bn + b) * Hn + i;
    float h = g_h[hidx];
    h = (1.f - z) * n + z * h;
    g_h[hidx] = h;
    g_hcat[b * K2n + g * Hn + i] = h;
}

// ---------------- logits: out[b][t][v] = hcat[b] . w_out[v] + b_out[v] -----
// grid = 250 row-blocks x 2 K-splits = 500 blocks, 128 threads, RT=128.
__global__ __launch_bounds__(128, 3) void logits_kernel(
    const float* __restrict__ wout, const float* __restrict__ bout,
    float* __restrict__ out, int t) {
    constexpr int RT = 128, KC = 16, KH = 1024, NK = KH / KC;  // NK=64
    const int rb = blockIdx.x % 250;
    const int ks = blockIdx.x / 250;
    const int rbase = rb * RT;
    const int koff = ks * KH;

    __shared__ __align__(16) float Ws[2][RT][20];
    __shared__ __align__(16) float As[2][Bn][20];

    const int tid = threadIdx.x;
    const int rg = tid >> 3, bg = tid & 7;   // compute map
    const int lr = tid >> 2, kq = tid & 3;   // load map

    const float* wbase = wout + (size_t)(rbase + lr) * K2n + koff + kq * 4;
    const float* arow = g_hcat + (size_t)lr * K2n + koff + kq * 4;

    ull acc[8][4];
#pragma unroll
    for (int i = 0; i < 8; ++i)
#pragma unroll
        for (int j = 0; j < 4; ++j) acc[i][j] = 0ULL;

    float4 wst[4]; float4 ast;
#pragma unroll
    for (int it = 0; it < 4; ++it)
        wst[it] = *(const float4*)(wbase + (size_t)it * 32 * K2n);
    ast = *(const float4*)(arow);

    int buf = 0;
    for (int c = 0; c < NK; ++c) {
#pragma unroll
        for (int it = 0; it < 4; ++it)
            *(float4*)&Ws[buf][lr + it * 32][kq * 4] = wst[it];
        *(float4*)&As[buf][lr][kq * 4] = ast;
        __syncthreads();
        if (c + 1 < NK) {
            int kc = (c + 1) * KC;
#pragma unroll
            for (int it = 0; it < 4; ++it)
                wst[it] = *(const float4*)(wbase + (size_t)it * 32 * K2n + kc);
            ast = *(const float4*)(arow + kc);
        }
#pragma unroll
        for (int kk = 0; kk < KC; kk += 4) {
            ulonglong2 av[4];
#pragma unroll
            for (int j = 0; j < 4; ++j)
                av[j] = *(const ulonglong2*)&As[buf][bg + 8 * j][kk];
#pragma unroll
            for (int i = 0; i < 8; ++i) {
                ulonglong2 wv = *(const ulonglong2*)&Ws[buf][rg + 16 * i][kk];
#pragma unroll
                for (int j = 0; j < 4; ++j) {
                    acc[i][j] = fma2(wv.x, av[j].x, acc[i][j]);
                    acc[i][j] = fma2(wv.y, av[j].y, acc[i][j]);
                }
            }
        }
        buf ^= 1;
    }

    if (ks == 0) {
#pragma unroll
        for (int i = 0; i < 8; ++i) {
            int v = rbase + rg + 16 * i;
            float bb = bout[v];
#pragma unroll
            for (int j = 0; j < 4; ++j) {
                int ba = bg + 8 * j;
                float2 f = *(float2*)&acc[i][j];
                out[(size_t)ba * Tn * Vn + (size_t)t * Vn + v] = f.x + f.y + bb;
            }
        }
    } else {
#pragma unroll
        for (int i = 0; i < 8; ++i) {
            int v = rbase + rg + 16 * i;
#pragma unroll
            for (int j = 0; j < 4; ++j) {
                int ba = bg + 8 * j;
                float2 f = *(float2*)&acc[i][j];
                g_part[(size_t)ba * Vn + v] = f.x + f.y;
            }
        }
    }
}

// ---------------- per-row max/argmax + logsumexp (sums the 2 partials) ------
__global__ __launch_bounds__(512) void reduce_kernel(const float* __restrict__ out,
                                                     int t) {
    const int b = blockIdx.x;
    const float4* rowA = (const float4*)(out + (size_t)b * Tn * Vn + (size_t)t * Vn);
    const float4* rowB = (const float4*)(g_part + (size_t)b * Vn);
    __shared__ float sm[512];
    __shared__ int si[512];
    const int tid = threadIdx.x;

    float m = -3.4e38f; int mi = 0;
    for (int i = tid; i < Vn / 4; i += 512) {
        float4 va = rowA[i], vb = rowB[i];
        float x0 = va.x + vb.x, x1 = va.y + vb.y, x2 = va.z + vb.z, x3 = va.w + vb.w;
        if (x0 > m) { m = x0; mi = 4 * i; }
        if (x1 > m) { m = x1; mi = 4 * i + 1; }
        if (x2 > m) { m = x2; mi = 4 * i + 2; }
        if (x3 > m) { m = x3; mi = 4 * i + 3; }
    }
    sm[tid] = m; si[tid] = mi;
    __syncthreads();
    for (int s = 256; s > 0; s >>= 1) {
        if (tid < s) {
            float vo = sm[tid + s]; int io = si[tid + s];
            if (vo > sm[tid] || (vo == sm[tid] && io < si[tid])) {
                sm[tid] = vo; si[tid] = io;
            }
        }
        __syncthreads();
    }
    float mx = sm[0]; int am = si[0];
    __syncthreads();

    float s = 0.f;
    for (int i = tid; i < Vn / 4; i += 512) {
        float4 va = rowA[i], vb = rowB[i];
        s += expf(va.x + vb.x - mx) + expf(va.y + vb.y - mx)
           + expf(va.z + vb.z - mx) + expf(va.w + vb.w - mx);
    }
    sm[tid] = s;
    __syncthreads();
    for (int st = 256; st > 0; st >>= 1) {
        if (tid < st) sm[tid] += sm[tid + st];
        __syncthreads();
    }
    if (tid == 0) {
        g_dec[b] = am;
        g_lse[b] = mx + logf(sm[0]);
    }
}

// ---------------- logits -> logp in place (adds partial, subtracts lse) -----
__global__ __launch_bounds__(256) void fix_kernel(float* __restrict__ out, int t) {
    int idx = blockIdx.x * blockDim.x + threadIdx.x;  // B * V/4 = 256000
    if (idx >= Bn * (Vn / 4)) return;
    int b = idx / (Vn / 4);
    int j = idx - b * (Vn / 4);
    float l = g_lse[b];
    float4* p = (float4*)(out + (size_t)b * Tn * Vn + (size_t)t * Vn + 4 * (size_t)j);
    const float4* q = (const float4*)(g_part + (size_t)b * Vn + 4 * (size_t)j);
    float4 v = *p; float4 w = *q;
    v.x = v.x + w.x - l; v.y = v.y + w.y - l;
    v.z = v.z + w.z - l; v.w = v.w + w.w - l;
    *p = v;
}

// ---------------- host ------------------------------------------------------
extern "C" void kernel_launch(void* const* d_in, const int* in_sizes, int n_in,
                              void* d_out, int out_size) {
    const int*   inputs = (const int*)d_in[0];
    const float* hidden = (const float*)d_in[1];
    const float* emb    = (const float*)d_in[2];
    const float* wihf   = (const float*)d_in[3];
    const float* whhf   = (const float*)d_in[4];
    const float* bihf   = (const float*)d_in[5];
    const float* bhhf   = (const float*)d_in[6];
    const float* wihb   = (const float*)d_in[7];
    const float* whhb   = (const float*)d_in[8];
    const float* bihb   = (const float*)d_in[9];
    const float* bhhb   = (const float*)d_in[10];
    const float* wout   = (const float*)d_in[11];
    const float* bout   = (const float*)d_in[12];
    float* out = (float*)d_out;

    init_kernel<<<256, 256>>>(inputs, hidden);
    for (int t = 0; t < Tn; ++t) {
        gates_kernel<<<192, 128>>>(emb, wihf, whhf, bihf, bhhf,
                                   wihb, whhb, bihb, bhhb);
        hupdate_kernel<<<256, 256>>>();
        logits_kernel<<<500, 128>>>(wout, bout, out, t);
        reduce_kernel<<<32, 512>>>(out, t);
        fix_kernel<<<1000, 256>>>(out, t);
    }
}

// round 14
// speedup vs baseline: 1.7375x; 1.0238x over previous
#include <cuda_runtime.h>

#define Bn  32
#define Hn  1024
#define Vn  32000
#define Tn  128
#define K2n 2048
#define H3n 3072

typedef unsigned long long ull;

// ---------------- scratch (device globals; no allocations allowed) ----------
__device__ float g_h[2 * Bn * Hn];      // [gru][b][H] current hidden
__device__ float g_hcat[Bn * K2n];      // [b][2H] concat(h_f, h_b)
__device__ float g_gi[2 * Bn * H3n];    // [gru][b][3H] partial ks=0 (with bias)
__device__ float g_gh[2 * Bn * H3n];
__device__ float g_giB[2 * Bn * H3n];   // partial ks=1
__device__ float g_ghB[2 * Bn * H3n];
__device__ float g_part[Bn * Vn];       // logits K-split partial (ks=1)
__device__ int   g_dec[Bn];             // current decoder input tokens
__device__ float g_lse[Bn];             // per-row logsumexp

__device__ __forceinline__ ull fma2(ull a, ull b, ull c) {
    ull d;
    asm("fma.rn.f32x2 %0, %1, %2, %3;" : "=l"(d) : "l"(a), "l"(b), "l"(c));
    return d;
}

__device__ __forceinline__ void cp16(unsigned sdst, const void* gsrc) {
    asm volatile("cp.async.ca.shared.global [%0], [%1], 16;"
                 :: "r"(sdst), "l"(gsrc));
}

// ---------------- init: h <- hidden, dec <- inputs[:,0] ---------------------
__global__ void init_kernel(const int* __restrict__ inputs,
                            const float* __restrict__ hidden) {
    int idx = blockIdx.x * blockDim.x + threadIdx.x;
    if (idx < 2 * Bn * Hn) g_h[idx] = hidden[idx];
    if (idx < Bn) g_dec[idx] = inputs[idx];
}

// ---------------- gates: gi/gh = {x,h} @ W^T (+b) for both GRUs -------------
// 4 matrices (3072 rows, K=1024), K-split 2 (KH=512). grid = 2*4*24 = 192.
__global__ __launch_bounds__(128, 3) void gates_kernel(
    const float* __restrict__ emb,
    const float* __restrict__ wihf, const float* __restrict__ whhf,
    const float* __restrict__ bihf, const float* __restrict__ bhhf,
    const float* __restrict__ wihb, const float* __restrict__ whhb,
    const float* __restrict__ bihb, const float* __restrict__ bhhb) {
    constexpr int RT = 128, KC = 16, K = Hn, KH = 512, NK = KH / KC;
    const int ks = blockIdx.x / 96;
    const int m4 = blockIdx.x % 96;
    const int m = m4 / 24;
    const int rbase = (m4 % 24) * RT;
    const int koff = ks * KH;

    const float* W; const float* bias; float* C; int useX = 0; int hoff = 0;
    if (m == 0)      { W = wihf; bias = bihf; C = (ks ? g_giB : g_gi);             useX = 1; }
    else if (m == 1) { W = whhf; bias = bhhf; C = (ks ? g_ghB : g_gh);             hoff = 0; }
    else if (m == 2) { W = wihb; bias = bihb; C = (ks ? g_giB : g_gi) + Bn * H3n;  useX = 1; }
    else             { W = whhb; bias = bhhb; C = (ks ? g_ghB : g_gh) + Bn * H3n;  hoff = Bn * Hn; }

    __shared__ __align__(16) float Ws[2][RT][20];
    __shared__ __align__(16) float As[2][Bn][20];

    const int tid = threadIdx.x;
    const int rg = tid >> 3, bg = tid & 7;   // compute map
    const int lr = tid >> 2, kq = tid & 3;   // load map

    const float* wbase = W + (size_t)(rbase + lr) * K + koff + kq * 4;
    const float* arow = (useX ? (emb + (size_t)g_dec[lr] * Hn)
                              : (g_h + hoff + lr * Hn)) + koff + kq * 4;

    ull acc[8][4];
#pragma unroll
    for (int i = 0; i < 8; ++i)
#pragma unroll
        for (int j = 0; j < 4; ++j) acc[i][j] = 0ULL;

    float4 wst[4]; float4 ast;
#pragma unroll
    for (int it = 0; it < 4; ++it)
        wst[it] = *(const float4*)(wbase + (size_t)it * 32 * K);
    ast = *(const float4*)(arow);

    int buf = 0;
    for (int c = 0; c < NK; ++c) {
#pragma unroll
        for (int it = 0; it < 4; ++it)
            *(float4*)&Ws[buf][lr + it * 32][kq * 4] = wst[it];
        *(float4*)&As[buf][lr][kq * 4] = ast;
        __syncthreads();
        if (c + 1 < NK) {
            int kc = (c + 1) * KC;
#pragma unroll
            for (int it = 0; it < 4; ++it)
                wst[it] = *(const float4*)(wbase + (size_t)it * 32 * K + kc);
            ast = *(const float4*)(arow + kc);
        }
#pragma unroll
        for (int kk = 0; kk < KC; kk += 4) {
            ulonglong2 av[4];
#pragma unroll
            for (int j = 0; j < 4; ++j)
                av[j] = *(const ulonglong2*)&As[buf][bg + 8 * j][kk];
#pragma unroll
            for (int i = 0; i < 8; ++i) {
                ulonglong2 wv = *(const ulonglong2*)&Ws[buf][rg + 16 * i][kk];
#pragma unroll
                for (int j = 0; j < 4; ++j) {
                    acc[i][j] = fma2(wv.x, av[j].x, acc[i][j]);
                    acc[i][j] = fma2(wv.y, av[j].y, acc[i][j]);
                }
            }
        }
        buf ^= 1;
    }

#pragma unroll
    for (int i = 0; i < 8; ++i) {
        int v = rbase + rg + 16 * i;
        float bb = (ks == 0) ? bias[v] : 0.f;
#pragma unroll
        for (int j = 0; j < 4; ++j) {
            int ba = bg + 8 * j;
            float2 f = *(float2*)&acc[i][j];
            C[(size_t)ba * H3n + v] = f.x + f.y + bb;
        }
    }
}

// ---------------- GRU gate combine + hidden update --------------------------
__global__ __launch_bounds__(256) void hupdate_kernel() {
    int idx = blockIdx.x * blockDim.x + threadIdx.x;  // 2*B*H = 65536
    int g = idx >> 15;
    int rem = idx & 32767;
    int b = rem >> 10;
    int i = rem & 1023;
    size_t base = ((size_t)g * Bn + b) * H3n;
    const float* gi  = g_gi  + base;
    const float* gh  = g_gh  + base;
    const float* giB = g_giB + base;
    const float* ghB = g_ghB + base;
    float ir = gi[i] + giB[i];
    float iz = gi[i + Hn] + giB[i + Hn];
    float inn = gi[i + 2 * Hn] + giB[i + 2 * Hn];
    float hr = gh[i] + ghB[i];
    float hz = gh[i + Hn] + ghB[i + Hn];
    float hn = gh[i + 2 * Hn] + ghB[i + 2 * Hn];
    float r = 1.f / (1.f + expf(-(ir + hr)));
    float z = 1.f / (1.f + expf(-(iz + hz)));
    float n = tanhf(inn + r * hn);
    int hidx = (g * Bn + b) * Hn + i;
    float h = g_h[hidx];
    h = (1.f - z) * n + z * h;
    g_h[hidx] = h;
    g_hcat[b * K2n + g * Hn + i] = h;
}

// ---------------- logits: out[b][t][v] = hcat[b] . w_out[v] + b_out[v] -----
// 256 threads, RT=224 rows x 32 batches, micro-tile 7x4, KC=32, 3-deep
// cp.async ring. grid = 143 row-tiles x 2 K-splits = 286 blocks (one wave,
// 2 blocks/SM). Dynamic smem: 3*(224+32)*36 floats = 108 KB.
#define L_RT   224
#define L_KC   32
#define L_PAD  36
#define L_WSZ  (L_RT * L_PAD)          // floats per W buffer
#define L_ASZ  (Bn * L_PAD)            // floats per A buffer
#define L_SMEM ((3 * (L_WSZ + L_ASZ)) * 4)

__global__ __launch_bounds__(256, 2) void logits_kernel(
    const float* __restrict__ wout, const float* __restrict__ bout,
    float* __restrict__ out, int t) {
    constexpr int KH = 1024, NK = KH / L_KC;   // 32 chunks
    const int rb = blockIdx.x % 143;
    const int ks = blockIdx.x / 143;
    const int rbase = rb * L_RT;
    const int koff = ks * KH;

    extern __shared__ __align__(16) float sm[];
    float* Wsm = sm;                   // [3][224][36]
    float* Asm = sm + 3 * L_WSZ;       // [3][32][36]

    const int tid = threadIdx.x;
    const int rg = tid >> 3, bg = tid & 7;    // compute map
    const int lr = tid >> 3, kq = tid & 7;    // load map (row, 16B quad)

    // global sources (row-clamped for the last tile)
    const float* wsrc[7];
#pragma unroll
    for (int it = 0; it < 7; ++it) {
        int gr = rbase + lr + it * 32;
        if (gr > Vn - 1) gr = Vn - 1;
        wsrc[it] = wout + (size_t)gr * K2n + koff + kq * 4;
    }
    const float* asrc = g_hcat + (size_t)lr * K2n + koff + kq * 4;

    // smem destinations (byte addresses)
    const unsigned sW = (unsigned)__cvta_generic_to_shared(
        &Wsm[(lr)*L_PAD + kq * 4]);
    const unsigned sA = (unsigned)__cvta_generic_to_shared(
        &Asm[(lr)*L_PAD + kq * 4]);

    ull acc[7][4];
#pragma unroll
    for (int i = 0; i < 7; ++i)
#pragma unroll
        for (int j = 0; j < 4; ++j) acc[i][j] = 0ULL;

    // prologue: issue chunks 0 and 1
#pragma unroll
    for (int p = 0; p < 2; ++p) {
        unsigned wb = sW + p * (L_WSZ * 4);
#pragma unroll
        for (int it = 0; it < 7; ++it)
            cp16(wb + it * (32 * L_PAD * 4), wsrc[it] + p * L_KC);
        cp16(sA + p * (L_ASZ * 4), asrc + p * L_KC);
        asm volatile("cp.async.commit_group;");
    }

    for (int c = 0; c < NK; ++c) {
        if (c + 1 < NK) asm volatile("cp.async.wait_group 1;");
        else            asm volatile("cp.async.wait_group 0;");
        __syncthreads();
        if (c + 2 < NK) {
            int nb = (c + 2) % 3;
            unsigned wb = sW + nb * (L_WSZ * 4);
#pragma unroll
            for (int it = 0; it < 7; ++it)
                cp16(wb + it * (32 * L_PAD * 4), wsrc[it] + (c + 2) * L_KC);
            cp16(sA + nb * (L_ASZ * 4), asrc + (c + 2) * L_KC);
            asm volatile("cp.async.commit_group;");
        }
        const int buf = c % 3;
        const float* wb = Wsm + buf * L_WSZ + rg * L_PAD;
        const float* ab = Asm + buf * L_ASZ + bg * L_PAD;
#pragma unroll
        for (int kk = 0; kk < L_KC; kk += 4) {
            ulonglong2 av[4];
#pragma unroll
            for (int j = 0; j < 4; ++j)
                av[j] = *(const ulonglong2*)(ab + 8 * j * L_PAD + kk);
#pragma unroll
            for (int i = 0; i < 7; ++i) {
                ulonglong2 wv = *(const ulonglong2*)(wb + 32 * i * L_PAD + kk);
#pragma unroll
                for (int j = 0; j < 4; ++j) {
                    acc[i][j] = fma2(wv.x, av[j].x, acc[i][j]);
                    acc[i][j] = fma2(wv.y, av[j].y, acc[i][j]);
                }
            }
        }
    }

    if (ks == 0) {
#pragma unroll
        for (int i = 0; i < 7; ++i) {
            int v = rbase + rg + 32 * i;
            if (v < Vn) {
                float bb = bout[v];
#pragma unroll
                for (int j = 0; j < 4; ++j) {
                    int ba = bg + 8 * j;
                    float2 f = *(float2*)&acc[i][j];
                    out[(size_t)ba * Tn * Vn + (size_t)t * Vn + v] = f.x + f.y + bb;
                }
            }
        }
    } else {
#pragma unroll
        for (int i = 0; i < 7; ++i) {
            int v = rbase + rg + 32 * i;
            if (v < Vn) {
#pragma unroll
                for (int j = 0; j < 4; ++j) {
                    int ba = bg + 8 * j;
                    float2 f = *(float2*)&acc[i][j];
                    g_part[(size_t)ba * Vn + v] = f.x + f.y;
                }
            }
        }
    }
}

// ---------------- per-row max/argmax + logsumexp (sums the 2 partials) ------
__global__ __launch_bounds__(512) void reduce_kernel(const float* __restrict__ out,
                                                     int t) {
    const int b = blockIdx.x;
    const float4* rowA = (const float4*)(out + (size_t)b * Tn * Vn + (size_t)t * Vn);
    const float4* rowB = (const float4*)(g_part + (size_t)b * Vn);
    __shared__ float sm[512];
    __shared__ int si[512];
    const int tid = threadIdx.x;

    float m = -3.4e38f; int mi = 0;
    for (int i = tid; i < Vn / 4; i += 512) {
        float4 va = rowA[i], vb = rowB[i];
        float x0 = va.x + vb.x, x1 = va.y + vb.y, x2 = va.z + vb.z, x3 = va.w + vb.w;
        if (x0 > m) { m = x0; mi = 4 * i; }
        if (x1 > m) { m = x1; mi = 4 * i + 1; }
        if (x2 > m) { m = x2; mi = 4 * i + 2; }
        if (x3 > m) { m = x3; mi = 4 * i + 3; }
    }
    sm[tid] = m; si[tid] = mi;
    __syncthreads();
    for (int s = 256; s > 0; s >>= 1) {
        if (tid < s) {
            float vo = sm[tid + s]; int io = si[tid + s];
            if (vo > sm[tid] || (vo == sm[tid] && io < si[tid])) {
                sm[tid] = vo; si[tid] = io;
            }
        }
        __syncthreads();
    }
    float mx = sm[0]; int am = si[0];
    __syncthreads();

    float s = 0.f;
    for (int i = tid; i < Vn / 4; i += 512) {
        float4 va = rowA[i], vb = rowB[i];
        s += expf(va.x + vb.x - mx) + expf(va.y + vb.y - mx)
           + expf(va.z + vb.z - mx) + expf(va.w + vb.w - mx);
    }
    sm[tid] = s;
    __syncthreads();
    for (int st = 256; st > 0; st >>= 1) {
        if (tid < st) sm[tid] += sm[tid + st];
        __syncthreads();
    }
    if (tid == 0) {
        g_dec[b] = am;
        g_lse[b] = mx + logf(sm[0]);
    }
}

// ---------------- logits -> logp in place (adds partial, subtracts lse) -----
__global__ __launch_bounds__(256) void fix_kernel(float* __restrict__ out, int t) {
    int idx = blockIdx.x * blockDim.x + threadIdx.x;  // B * V/4 = 256000
    if (idx >= Bn * (Vn / 4)) return;
    int b = idx / (Vn / 4);
    int j = idx - b * (Vn / 4);
    float l = g_lse[b];
    float4* p = (float4*)(out + (size_t)b * Tn * Vn + (size_t)t * Vn + 4 * (size_t)j);
    const float4* q = (const float4*)(g_part + (size_t)b * Vn + 4 * (size_t)j);
    float4 v = *p; float4 w = *q;
    v.x = v.x + w.x - l; v.y = v.y + w.y - l;
    v.z = v.z + w.z - l; v.w = v.w + w.w - l;
    *p = v;
}

// ---------------- host ------------------------------------------------------
extern "C" void kernel_launch(void* const* d_in, const int* in_sizes, int n_in,
                              void* d_out, int out_size) {
    const int*   inputs = (const int*)d_in[0];
    const float* hidden = (const float*)d_in[1];
    const float* emb    = (const float*)d_in[2];
    const float* wihf   = (const float*)d_in[3];
    const float* whhf   = (const float*)d_in[4];
    const float* bihf   = (const float*)d_in[5];
    const float* bhhf   = (const float*)d_in[6];
    const float* wihb   = (const float*)d_in[7];
    const float* whhb   = (const float*)d_in[8];
    const float* bihb   = (const float*)d_in[9];
    const float* bhhb   = (const float*)d_in[10];
    const float* wout   = (const float*)d_in[11];
    const float* bout   = (const float*)d_in[12];
    float* out = (float*)d_out;

    cudaFuncSetAttribute(logits_kernel,
                         cudaFuncAttributeMaxDynamicSharedMemorySize, L_SMEM);

    init_kernel<<<256, 256>>>(inputs, hidden);
    for (int t = 0; t < Tn; ++t) {
        gates_kernel<<<192, 128>>>(emb, wihf, whhf, bihf, bhhf,
                                   wihb, whhb, bihb, bhhb);
        hupdate_kernel<<<256, 256>>>();
        logits_kernel<<<286, 256, L_SMEM>>>(wout, bout, out, t);
        reduce_kernel<<<32, 512>>>(out, t);
        fix_kernel<<<1000, 256>>>(out, t);
    }
}

// round 16
// speedup vs baseline: 1.7878x; 1.0290x over previous
#include <cuda_runtime.h>

#define Bn  32
#define Hn  1024
#define Vn  32000
#define Tn  128
#define K2n 2048
#define H3n 3072

typedef unsigned long long ull;
typedef unsigned int u32;

// ---------------- scratch (device globals; no allocations allowed) ----------
__device__ float g_h[2 * Bn * Hn];      // [gru][b][H] current hidden
__device__ float g_hcat[Bn * K2n];      // [b][2H] concat(h_f, h_b) fp32
__device__ float g_bhi[Bn * K2n];       // hcat tf32 hi (as fp32 bits)
__device__ float g_blo[Bn * K2n];       // hcat tf32 lo residual
__device__ float g_gi[2 * Bn * H3n];    // gates partial ks=0 (with bias)
__device__ float g_gh[2 * Bn * H3n];
__device__ float g_giB[2 * Bn * H3n];   // gates partial ks=1
__device__ float g_ghB[2 * Bn * H3n];
__device__ int   g_dec[Bn];             // current decoder input tokens
__device__ float g_lse[Bn];             // per-row logsumexp

__device__ __forceinline__ ull fma2(ull a, ull b, ull c) {
    ull d;
    asm("fma.rn.f32x2 %0, %1, %2, %3;" : "=l"(d) : "l"(a), "l"(b), "l"(c));
    return d;
}

__device__ __forceinline__ void cp16(u32 sdst, const void* gsrc) {
    asm volatile("cp.async.ca.shared.global [%0], [%1], 16;"
                 :: "r"(sdst), "l"(gsrc));
}

__device__ __forceinline__ u32 tf32_of(float x) {
    u32 r;
    asm("cvt.rna.tf32.f32 %0, %1;" : "=r"(r) : "f"(x));
    return r;
}

#define MMA_TF32(c0, c1, c2, c3, a0, a1, a2, a3, b0, b1)                    \
    asm volatile(                                                            \
        "mma.sync.aligned.m16n8k8.row.col.f32.tf32.tf32.f32 "               \
        "{%0,%1,%2,%3}, {%4,%5,%6,%7}, {%8,%9}, {%0,%1,%2,%3};"             \
        : "+f"(c0), "+f"(c1), "+f"(c2), "+f"(c3)                             \
        : "r"(a0), "r"(a1), "r"(a2), "r"(a3), "r"(b0), "r"(b1))

// ---------------- init: h <- hidden, dec <- inputs[:,0] ---------------------
__global__ void init_kernel(const int* __restrict__ inputs,
                            const float* __restrict__ hidden) {
    int idx = blockIdx.x * blockDim.x + threadIdx.x;
    if (idx < 2 * Bn * Hn) g_h[idx] = hidden[idx];
    if (idx < Bn) g_dec[idx] = inputs[idx];
}

// ---------------- gates: gi/gh = {x,h} @ W^T (+b) for both GRUs (fp32) ------
__global__ __launch_bounds__(128, 3) void gates_kernel(
    const float* __restrict__ emb,
    const float* __restrict__ wihf, const float* __restrict__ whhf,
    const float* __restrict__ bihf, const float* __restrict__ bhhf,
    const float* __restrict__ wihb, const float* __restrict__ whhb,
    const float* __restrict__ bihb, const float* __restrict__ bhhb) {
    constexpr int RT = 128, KC = 16, K = Hn, KH = 512, NK = KH / KC;
    const int ks = blockIdx.x / 96;
    const int m4 = blockIdx.x % 96;
    const int m = m4 / 24;
    const int rbase = (m4 % 24) * RT;
    const int koff = ks * KH;

    const float* W; const float* bias; float* C; int useX = 0; int hoff = 0;
    if (m == 0)      { W = wihf; bias = bihf; C = (ks ? g_giB : g_gi);             useX = 1; }
    else if (m == 1) { W = whhf; bias = bhhf; C = (ks ? g_ghB : g_gh);             hoff = 0; }
    else if (m == 2) { W = wihb; bias = bihb; C = (ks ? g_giB : g_gi) + Bn * H3n;  useX = 1; }
    else             { W = whhb; bias = bhhb; C = (ks ? g_ghB : g_gh) + Bn * H3n;  hoff = Bn * Hn; }

    __shared__ __align__(16) float Ws[2][RT][20];
    __shared__ __align__(16) float As[2][Bn][20];

    const int tid = threadIdx.x;
    const int rg = tid >> 3, bg = tid & 7;
    const int lr = tid >> 2, kq = tid & 3;

    const float* wbase = W + (size_t)(rbase + lr) * K + koff + kq * 4;
    const float* arow = (useX ? (emb + (size_t)g_dec[lr] * Hn)
                              : (g_h + hoff + lr * Hn)) + koff + kq * 4;

    ull acc[8][4];
#pragma unroll
    for (int i = 0; i < 8; ++i)
#pragma unroll
        for (int j = 0; j < 4; ++j) acc[i][j] = 0ULL;

    float4 wst[4]; float4 ast;
#pragma unroll
    for (int it = 0; it < 4; ++it)
        wst[it] = *(const float4*)(wbase + (size_t)it * 32 * K);
    ast = *(const float4*)(arow);

    int buf = 0;
    for (int c = 0; c < NK; ++c) {
#pragma unroll
        for (int it = 0; it < 4; ++it)
            *(float4*)&Ws[buf][lr + it * 32][kq * 4] = wst[it];
        *(float4*)&As[buf][lr][kq * 4] = ast;
        __syncthreads();
        if (c + 1 < NK) {
            int kc = (c + 1) * KC;
#pragma unroll
            for (int it = 0; it < 4; ++it)
                wst[it] = *(const float4*)(wbase + (size_t)it * 32 * K + kc);
            ast = *(const float4*)(arow + kc);
        }
#pragma unroll
        for (int kk = 0; kk < KC; kk += 4) {
            ulonglong2 av[4];
#pragma unroll
            for (int j = 0; j < 4; ++j)
                av[j] = *(const ulonglong2*)&As[buf][bg + 8 * j][kk];
#pragma unroll
            for (int i = 0; i < 8; ++i) {
                ulonglong2 wv = *(const ulonglong2*)&Ws[buf][rg + 16 * i][kk];
#pragma unroll
                for (int j = 0; j < 4; ++j) {
                    acc[i][j] = fma2(wv.x, av[j].x, acc[i][j]);
                    acc[i][j] = fma2(wv.y, av[j].y, acc[i][j]);
                }
            }
        }
        buf ^= 1;
    }

#pragma unroll
    for (int i = 0; i < 8; ++i) {
        int v = rbase + rg + 16 * i;
        float bb = (ks == 0) ? bias[v] : 0.f;
#pragma unroll
        for (int j = 0; j < 4; ++j) {
            int ba = bg + 8 * j;
            float2 f = *(float2*)&acc[i][j];
            C[(size_t)ba * H3n + v] = f.x + f.y + bb;
        }
    }
}

// ---------------- GRU combine + hidden update + tf32 split of hcat ----------
__global__ __launch_bounds__(256) void hupdate_kernel() {
    int idx = blockIdx.x * blockDim.x + threadIdx.x;  // 2*B*H = 65536
    int g = idx >> 15;
    int rem = idx & 32767;
    int b = rem >> 10;
    int i = rem & 1023;
    size_t base = ((size_t)g * Bn + b) * H3n;
    const float* gi  = g_gi  + base;
    const float* gh  = g_gh  + base;
    const float* giB = g_giB + base;
    const float* ghB = g_ghB + base;
    float ir = gi[i] + giB[i];
    float iz = gi[i + Hn] + giB[i + Hn];
    float inn = gi[i + 2 * Hn] + giB[i + 2 * Hn];
    float hr = gh[i] + ghB[i];
    float hz = gh[i + Hn] + ghB[i + Hn];
    float hn = gh[i + 2 * Hn] + ghB[i + 2 * Hn];
    float r = 1.f / (1.f + expf(-(ir + hr)));
    float z = 1.f / (1.f + expf(-(iz + hz)));
    float n = tanhf(inn + r * hn);
    int hidx = (g * Bn + b) * Hn + i;
    float h = g_h[hidx];
    h = (1.f - z) * n + z * h;
    g_h[hidx] = h;
    int ci = b * K2n + g * Hn + i;
    g_hcat[ci] = h;
    float hhi = __uint_as_float(tf32_of(h));
    g_bhi[ci] = hhi;
    g_blo[ci] = __uint_as_float(tf32_of(h - hhi));
}

// ---------------- logits via mma.sync tf32 hi/lo split ----------------------
// grid = 286 blocks (112 V-rows), 256 threads (warps 0-6 compute m16 each).
// K=2048 in 64 chunks of 32; 3-deep cp.async ring.
// Buffer: W fp32 112x36 | Bhi 32x36 | Blo 32x36 floats (25344 B), x3 = 76032.
#define LWF    4032                 // W floats per buffer (112*36)
#define LBHF   1152                 // B floats (32*36)
#define LBUF_F 6336                 // floats per buffer
#define LBUF_B 25344                // bytes per buffer
#define L_SMEM (3 * LBUF_B)

__global__ __launch_bounds__(256, 2) void logits_tc_kernel(
    const float* __restrict__ wout, const float* __restrict__ bout,
    float* __restrict__ out, int t) {
    constexpr int NCH = 64;
    extern __shared__ __align__(16) float sm[];
    const int tid = threadIdx.x, wid = tid >> 5, lid = tid & 31;
    const int g = lid >> 2, q = lid & 3;
    const int rbase = blockIdx.x * 112;

    // loader maps
    const int wlr = tid >> 1, wqp = tid & 1;        // w: row, quad parity
    int wrow = rbase + wlr; if (wrow > Vn - 1) wrow = Vn - 1;
    const float* wsrc = wout + (size_t)wrow * K2n + wqp * 4;
    const int blr = tid >> 3, bq = tid & 7;         // b: row, quad
    const float* bhsrc = g_bhi + blr * K2n + bq * 4;
    const float* blsrc = g_blo + blr * K2n + bq * 4;

    const u32 sbase = (u32)__cvta_generic_to_shared(sm);
    const u32 wdst = sbase + wlr * 144 + wqp * 16;
    const u32 bhd = sbase + LWF * 4 + blr * 144 + bq * 16;
    const u32 bld = sbase + (LWF + LBHF) * 4 + blr * 144 + bq * 16;

    // accumulators with bias folded in
    const int v0 = rbase + 16 * wid + g;
    const int v8 = v0 + 8;
    float acc[4][4];
    {
        float b0 = (wid < 7 && v0 < Vn) ? bout[v0] : 0.f;
        float b8 = (wid < 7 && v8 < Vn) ? bout[v8] : 0.f;
#pragma unroll
        for (int nt = 0; nt < 4; ++nt) {
            acc[nt][0] = b0; acc[nt][1] = b0;
            acc[nt][2] = b8; acc[nt][3] = b8;
        }
    }

    // prologue: chunks 0, 1
#pragma unroll
    for (int p = 0; p < 2; ++p) {
        u32 bb = p * LBUF_B;
        if (wlr < 112) {
            const float* s = wsrc + p * 32;
#pragma unroll
            for (int i = 0; i < 4; ++i)
                cp16(wdst + bb + i * 32, s + i * 8);
        }
        cp16(bhd + bb, bhsrc + p * 32);
        cp16(bld + bb, blsrc + p * 32);
        asm volatile("cp.async.commit_group;" ::: "memory");
    }

    for (int c = 0; c < NCH; ++c) {
        if (c + 1 < NCH) asm volatile("cp.async.wait_group 1;" ::: "memory");
        else             asm volatile("cp.async.wait_group 0;" ::: "memory");
        __syncthreads();
        if (c + 2 < NCH) {
            u32 bb = ((c + 2) % 3) * LBUF_B;
            int kc = (c + 2) * 32;
            if (wlr < 112) {
                const float* s = wsrc + kc;
#pragma unroll
                for (int i = 0; i < 4; ++i)
                    cp16(wdst + bb + i * 32, s + i * 8);
            }
            cp16(bhd + bb, bhsrc + kc);
            cp16(bld + bb, blsrc + kc);
            asm volatile("cp.async.commit_group;" ::: "memory");
        }
        if (wid < 7) {
            const float* Wb = sm + (c % 3) * LBUF_F;
            const u32* BH = (const u32*)(Wb + LWF);
            const u32* BL = (const u32*)(Wb + LWF + LBHF);
            const float* wr0 = Wb + (16 * wid + g) * 36;
            const float* wr8 = wr0 + 8 * 36;
#pragma unroll
            for (int kk = 0; kk < 32; kk += 8) {
                float x0 = wr0[kk + q];
                float x1 = wr8[kk + q];
                float x2 = wr0[kk + q + 4];
                float x3 = wr8[kk + q + 4];
                u32 ah0 = tf32_of(x0), ah1 = tf32_of(x1);
                u32 ah2 = tf32_of(x2), ah3 = tf32_of(x3);
                u32 al0 = tf32_of(x0 - __uint_as_float(ah0));
                u32 al1 = tf32_of(x1 - __uint_as_float(ah1));
                u32 al2 = tf32_of(x2 - __uint_as_float(ah2));
                u32 al3 = tf32_of(x3 - __uint_as_float(ah3));
#pragma unroll
                for (int nt = 0; nt < 4; ++nt) {
                    const u32* bp = BH + (8 * nt + g) * 36 + kk;
                    const u32* lp = BL + (8 * nt + g) * 36 + kk;
                    u32 bh0 = bp[q], bh1 = bp[q + 4];
                    u32 bl0 = lp[q], bl1 = lp[q + 4];
                    MMA_TF32(acc[nt][0], acc[nt][1], acc[nt][2], acc[nt][3],
                             ah0, ah1, ah2, ah3, bh0, bh1);
                    MMA_TF32(acc[nt][0], acc[nt][1], acc[nt][2], acc[nt][3],
                             ah0, ah1, ah2, ah3, bl0, bl1);
                    MMA_TF32(acc[nt][0], acc[nt][1], acc[nt][2], acc[nt][3],
                             al0, al1, al2, al3, bh0, bh1);
                }
            }
        }
    }

    if (wid < 7) {
        float* op = out + (size_t)t * Vn;
#pragma unroll
        for (int nt = 0; nt < 4; ++nt) {
            const int ba = 8 * nt + 2 * q;
            if (v0 < Vn) {
                op[(size_t)ba * Tn * Vn + v0] = acc[nt][0];
                op[(size_t)(ba + 1) * Tn * Vn + v0] = acc[nt][1];
            }
            if (v8 < Vn) {
                op[(size_t)ba * Tn * Vn + v8] = acc[nt][2];
                op[(size_t)(ba + 1) * Tn * Vn + v8] = acc[nt][3];
            }
        }
    }
}

// ---------------- reduce: max + exact-fp32 argmax of candidates + lse -------
__global__ __launch_bounds__(512) void reduce_kernel(const float* __restrict__ out,
                                                     const float* __restrict__ wout,
                                                     const float* __restrict__ bout,
                                                     int t) {
    const int b = blockIdx.x;
    const float* row = out + (size_t)b * Tn * Vn + (size_t)t * Vn;
    const float4* row4 = (const float4*)row;
    __shared__ float sm[512];
    __shared__ int cand[32];
    __shared__ int cnum;
    const int tid = threadIdx.x;

    // pass 1: max value
    float m = -3.4e38f;
    for (int i = tid; i < Vn / 4; i += 512) {
        float4 v = row4[i];
        m = fmaxf(m, fmaxf(fmaxf(v.x, v.y), fmaxf(v.z, v.w)));
    }
    sm[tid] = m;
    __syncthreads();
    for (int s = 256; s > 0; s >>= 1) {
        if (tid < s) sm[tid] = fmaxf(sm[tid], sm[tid + s]);
        __syncthreads();
    }
    const float mx = sm[0];
    __syncthreads();

    // pass 2: candidates within margin; exact fp32 recompute decides argmax
    if (tid == 0) cnum = 0;
    __syncthreads();
    const float thr = mx - 0.01f;
    for (int i = tid; i < Vn; i += 512) {
        if (row[i] >= thr) {
            int p = atomicAdd(&cnum, 1);
            if (p < 32) cand[p] = i;
        }
    }
    __syncthreads();
    const int nc = (cnum < 32) ? cnum : 32;

    float bestv = -3.4e38f;
    int besti = Vn;
    const float4 ha = ((const float4*)(g_hcat + (size_t)b * K2n))[tid];
    for (int j = 0; j < nc; ++j) {
        const int v = cand[j];
        const float4 w = ((const float4*)(wout + (size_t)v * K2n))[tid];
        sm[tid] = ha.x * w.x + ha.y * w.y + ha.z * w.z + ha.w * w.w;
        __syncthreads();
        for (int s = 256; s > 0; s >>= 1) {
            if (tid < s) sm[tid] += sm[tid + s];
            __syncthreads();
        }
        const float val = sm[0] + bout[v];
        if (val > bestv || (val == bestv && v < besti)) { bestv = val; besti = v; }
        __syncthreads();
    }

    // pass 3: logsumexp
    float s = 0.f;
    for (int i = tid; i < Vn / 4; i += 512) {
        float4 v = row4[i];
        s += expf(v.x - mx) + expf(v.y - mx) + expf(v.z - mx) + expf(v.w - mx);
    }
    sm[tid] = s;
    __syncthreads();
    for (int st = 256; st > 0; st >>= 1) {
        if (tid < st) sm[tid] += sm[tid + st];
        __syncthreads();
    }
    if (tid == 0) {
        g_dec[b] = besti;
        g_lse[b] = mx + logf(sm[0]);
    }
}

// ---------------- logits -> logp in place -----------------------------------
__global__ __launch_bounds__(256) void fix_kernel(float* __restrict__ out, int t) {
    int idx = blockIdx.x * blockDim.x + threadIdx.x;  // B * V/4 = 256000
    if (idx >= Bn * (Vn / 4)) return;
    int b = idx / (Vn / 4);
    int j = idx - b * (Vn / 4);
    float l = g_lse[b];
    float4* p = (float4*)(out + (size_t)b * Tn * Vn + (size_t)t * Vn + 4 * (size_t)j);
    float4 v = *p;
    v.x -= l; v.y -= l; v.z -= l; v.w -= l;
    *p = v;
}

// ---------------- host ------------------------------------------------------
extern "C" void kernel_launch(void* const* d_in, const int* in_sizes, int n_in,
                              void* d_out, int out_size) {
    const int*   inputs = (const int*)d_in[0];
    const float* hidden = (const float*)d_in[1];
    const float* emb    = (const float*)d_in[2];
    const float* wihf   = (const float*)d_in[3];
    const float* whhf   = (const float*)d_in[4];
    const float* bihf   = (const float*)d_in[5];
    const float* bhhf   = (const float*)d_in[6];
    const float* wihb   = (const float*)d_in[7];
    const float* whhb   = (const float*)d_in[8];
    const float* bihb   = (const float*)d_in[9];
    const float* bhhb   = (const float*)d_in[10];
    const float* wout   = (const float*)d_in[11];
    const float* bout   = (const float*)d_in[12];
    float* out = (float*)d_out;

    cudaFuncSetAttribute(logits_tc_kernel,
                         cudaFuncAttributeMaxDynamicSharedMemorySize, L_SMEM);

    init_kernel<<<256, 256>>>(inputs, hidden);
    for (int t = 0; t < Tn; ++t) {
        gates_kernel<<<192, 128>>>(emb, wihf, whhf, bihf, bhhf,
                                   wihb, whhb, bihb, bhhb);
        hupdate_kernel<<<256, 256>>>();
        logits_tc_kernel<<<286, 256, L_SMEM>>>(wout, bout, out, t);
        reduce_kernel<<<32, 512>>>(out, wout, bout, t);
        fix_kernel<<<1000, 256>>>(out, t);
    }
}